// round 2
// baseline (speedup 1.0000x reference)
#include <cuda_runtime.h>

#define AR_P 64
#define AR_T 65536
#define CHUNK_L 8192
#define N_CHUNKS 8   // AR_T / CHUNK_L

__device__ float g_hpad[AR_P + CHUNK_L];                 // h with 64 leading zeros
__device__ __align__(16) float g_H[CHUNK_L];             // inclusive prefix sum of h
__device__ float g_phi[N_CHUNKS][AR_P];                  // per-chunk boundary projections
__device__ __align__(16) float g_means[AR_T];

// ---------------------------------------------------------------------------
// Kernel 1 (single block): impulse response via doubling, prefix sum,
// and per-chunk boundary states.
// ---------------------------------------------------------------------------
__global__ __launch_bounds__(1024) void k1_prep(const float* __restrict__ params,
                                                const float* __restrict__ bias) {
    __shared__ float Pp[2 * AR_P];            // params padded with 64 zeros
    __shared__ float hs[AR_P + CHUNK_L];      // padded impulse response
    __shared__ float phi[AR_P];
    __shared__ float red[32];
    __shared__ float stA[AR_P], stB[AR_P];

    const int tid = threadIdx.x;
    const float bv = bias[0];

    if (tid < 2 * AR_P) Pp[tid] = (tid < AR_P) ? params[tid] : 0.0f;
    if (tid < AR_P) hs[tid] = 0.0f;           // left zero pad (h_{-64..-1}=0)
    if (tid == 0) hs[AR_P] = 1.0f;            // h_0 = 1
    __syncthreads();

    // --- doubling: extend h from [0,n) to [0,2n) ---
    for (int n = 1; n < CHUNK_L; n <<= 1) {
        // phi_i = sum_j a_{i+j} * h_{n-1-j}
        if (tid < AR_P) {
            float acc = 0.0f;
            #pragma unroll 8
            for (int j = 0; j < AR_P; j++)
                acc += Pp[tid + j] * hs[AR_P + n - 1 - j];
            phi[tid] = acc;
        }
        __syncthreads();
        if (n <= 512) {
            if (tid < n) {
                float acc = 0.0f;
                #pragma unroll 8
                for (int i = 0; i < AR_P; i++)
                    acc += hs[AR_P + tid - i] * phi[i];
                hs[AR_P + n + tid] = acc;
            }
        } else {
            // 4 consecutive outputs per thread, sliding register window
            for (int m0 = tid * 4; m0 < n; m0 += 4096) {
                float a0 = 0.f, a1 = 0.f, a2 = 0.f, a3 = 0.f;
                float w0 = hs[AR_P + m0 + 3], w1 = hs[AR_P + m0 + 2];
                float w2 = hs[AR_P + m0 + 1], w3 = hs[AR_P + m0];
                #pragma unroll
                for (int i = 0; i < AR_P; i++) {
                    const float ph = phi[i];
                    a3 += w0 * ph; a2 += w1 * ph; a1 += w2 * ph; a0 += w3 * ph;
                    w0 = w1; w1 = w2; w2 = w3;
                    w3 = hs[AR_P + m0 - i - 1];
                }
                hs[AR_P + n + m0 + 0] = a0; hs[AR_P + n + m0 + 1] = a1;
                hs[AR_P + n + m0 + 2] = a2; hs[AR_P + n + m0 + 3] = a3;
            }
        }
        __syncthreads();
    }

    // write padded h to global
    for (int q = tid; q < AR_P + CHUNK_L; q += 1024) g_hpad[q] = hs[q];

    // --- inclusive prefix sum of h -> g_H (8 elements per thread) ---
    float v[8];
    float s = 0.0f;
    #pragma unroll
    for (int k = 0; k < 8; k++) { v[k] = hs[AR_P + tid * 8 + k]; s += v[k]; }
    float ss = s;
    #pragma unroll
    for (int o = 1; o < 32; o <<= 1) {
        const float t2 = __shfl_up_sync(0xffffffffu, ss, o);
        if ((tid & 31) >= o) ss += t2;
    }
    if ((tid & 31) == 31) red[tid >> 5] = ss;
    __syncthreads();
    if (tid < 32) {
        float ws = red[tid];
        #pragma unroll
        for (int o = 1; o < 32; o <<= 1) {
            const float t2 = __shfl_up_sync(0xffffffffu, ws, o);
            if (tid >= o) ws += t2;
        }
        red[tid] = ws;
    }
    __syncthreads();
    float run = (ss - s) + ((tid >= 32) ? red[(tid >> 5) - 1] : 0.0f);
    #pragma unroll
    for (int k = 0; k < 8; k++) { run += v[k]; g_H[tid * 8 + k] = run; }
    __syncthreads();

    // --- sequential hop over the 8 chunk-boundary states ---
    if (tid < AR_P) stA[tid] = 0.0f;          // state[j] = x_{cL-1-j}, chunk 0: zeros
    __syncthreads();
    float* scur = stA;
    float* snew = stB;
    for (int c = 0; c < N_CHUNKS; c++) {
        if (tid < AR_P) {
            float acc = 0.0f;
            #pragma unroll 8
            for (int j = 0; j < AR_P; j++) acc += Pp[tid + j] * scur[j];
            phi[tid] = acc;
            g_phi[c][tid] = acc;
        }
        __syncthreads();
        if (c < N_CHUNKS - 1) {
            if (tid < AR_P) {
                const int m = CHUNK_L - 1 - tid;  // new state[j] = x_{(c+1)L-1-j}
                float acc = 0.0f;
                #pragma unroll 8
                for (int i = 0; i < AR_P; i++) acc += hs[AR_P + m - i] * phi[i];
                snew[tid] = acc + bv * g_H[m];
            }
            __syncthreads();
            float* tmp = scur; scur = snew; snew = tmp;
        }
    }
}

// ---------------------------------------------------------------------------
// Kernel 2: fill all means. grid = N_CHUNKS*8 blocks x 256 threads,
// 4 consecutive outputs per thread (1024 outputs per block).
// ---------------------------------------------------------------------------
__global__ __launch_bounds__(256) void k2_means(const float* __restrict__ bias) {
    const int c = blockIdx.x >> 3;
    const int part = blockIdx.x & 7;
    const int m0base = part * 1024;

    __shared__ float phi[AR_P];
    __shared__ float hw[1088 + 4];   // h_{m0base-64 .. m0base+1023}

    const int tid = threadIdx.x;
    if (tid < AR_P) phi[tid] = g_phi[c][tid];
    for (int q = tid; q < 1088; q += 256) hw[q] = g_hpad[m0base + q];
    __syncthreads();

    const float bv = bias[0];
    const int d = tid * 4;
    float a0 = 0.f, a1 = 0.f, a2 = 0.f, a3 = 0.f;
    float w0 = hw[64 + d + 3], w1 = hw[64 + d + 2];
    float w2 = hw[64 + d + 1], w3 = hw[64 + d];
    #pragma unroll
    for (int i = 0; i < AR_P; i++) {
        const float ph = phi[i];
        a3 += w0 * ph; a2 += w1 * ph; a1 += w2 * ph; a0 += w3 * ph;
        w0 = w1; w1 = w2; w2 = w3;
        w3 = hw[64 + d - i - 1];
    }
    const int m = m0base + d;
    const float4 Hv = *reinterpret_cast<const float4*>(&g_H[m]);
    float4 r;
    r.x = fmaf(bv, Hv.x, a0);
    r.y = fmaf(bv, Hv.y, a1);
    r.z = fmaf(bv, Hv.z, a2);
    r.w = fmaf(bv, Hv.w, a3);
    *reinterpret_cast<float4*>(&g_means[c * CHUNK_L + m]) = r;
}

// ---------------------------------------------------------------------------
// Kernel 3: out[b,t] = means[t] + 0.3*noise[b,t]  (float4 streaming)
// ---------------------------------------------------------------------------
__global__ __launch_bounds__(256) void k3_out(const float4* __restrict__ noise,
                                              float4* __restrict__ out) {
    const int idx = blockIdx.x * 256 + threadIdx.x;
    const int t4 = idx & (AR_T / 4 - 1);
    const float4 nz = noise[idx];
    const float4 mn = reinterpret_cast<const float4*>(g_means)[t4];
    float4 r;
    r.x = fmaf(0.3f, nz.x, mn.x);
    r.y = fmaf(0.3f, nz.y, mn.y);
    r.z = fmaf(0.3f, nz.z, mn.z);
    r.w = fmaf(0.3f, nz.w, mn.w);
    out[idx] = r;
}

extern "C" void kernel_launch(void* const* d_in, const int* in_sizes, int n_in,
                              void* d_out, int out_size) {
    // identify inputs by element count (params=64, bias=1, noise=256*65536)
    const float* params = nullptr;
    const float* bias   = nullptr;
    const float* noise  = nullptr;
    for (int i = 0; i < n_in; i++) {
        if (in_sizes[i] == AR_P)      params = (const float*)d_in[i];
        else if (in_sizes[i] == 1)    bias   = (const float*)d_in[i];
        else                          noise  = (const float*)d_in[i];
    }

    k1_prep<<<1, 1024>>>(params, bias);
    k2_means<<<N_CHUNKS * 8, 256>>>(bias);

    const int total4 = out_size / 4;          // 4,194,304 float4s
    k3_out<<<total4 / 256, 256>>>((const float4*)noise, (float4*)d_out);
}

// round 3
// speedup vs baseline: 1.2662x; 1.2662x over previous
#include <cuda_runtime.h>

#define AR_P 64
#define AR_T 65536
#define CHUNK_L 8192
#define N_CHUNKS 8   // AR_T / CHUNK_L

__device__ __align__(16) float g_hpad[AR_P + CHUNK_L];   // h with 64 leading zeros
__device__ __align__(16) float g_H[CHUNK_L];             // inclusive prefix sum of h
__device__ float g_phi[N_CHUNKS][AR_P];                  // per-chunk boundary projections
__device__ __align__(16) float g_means[AR_T];

// ---------------------------------------------------------------------------
// Conflict-free 64-tap convolution for 4 consecutive outputs.
// v[k] tracked as registers; window loaded via float4 (LDS.128, byte-bound).
// Computes out[r] = sum_{i=0}^{63} src[base0 + r - i] * phi[i], r = 0..3,
// where src is a 16B-aligned shared array and base0 is a multiple of 4.
// ---------------------------------------------------------------------------
__device__ __forceinline__ void conv4_f4(const float* __restrict__ src, int base0,
                                         const float* __restrict__ phi,
                                         float& a0, float& a1, float& a2, float& a3) {
    const float4 va = *reinterpret_cast<const float4*>(&src[base0]);
    const float4 vb = *reinterpret_cast<const float4*>(&src[base0 - 4]);
    float v0 = vb.x, v1 = vb.y, v2 = vb.z, v3 = vb.w;
    float v4 = va.x, v5 = va.y, v6 = va.z, v7 = va.w;
    a0 = 0.f; a1 = 0.f; a2 = 0.f; a3 = 0.f;
    #pragma unroll
    for (int i4 = 0; i4 < 16; i4++) {
        if (i4 > 0) {
            v4 = v0; v5 = v1; v6 = v2; v7 = v3;
            const float4 nv = *reinterpret_cast<const float4*>(&src[base0 - 4 - 4 * i4]);
            v0 = nv.x; v1 = nv.y; v2 = nv.z; v3 = nv.w;
        }
        const float4 p = *reinterpret_cast<const float4*>(&phi[4 * i4]);
        a0 += v4 * p.x; a1 += v5 * p.x; a2 += v6 * p.x; a3 += v7 * p.x;
        a0 += v3 * p.y; a1 += v4 * p.y; a2 += v5 * p.y; a3 += v6 * p.y;
        a0 += v2 * p.z; a1 += v3 * p.z; a2 += v4 * p.z; a3 += v5 * p.z;
        a0 += v1 * p.w; a1 += v2 * p.w; a2 += v3 * p.w; a3 += v4 * p.w;
    }
}

// 4-way-split 64-tap dot: sum_{j=0}^{63} a[j] * b_rev(j), serial chain ~64 cyc.
__device__ __forceinline__ float dot64_4acc_fwd_rev(const float* __restrict__ A, int abase,
                                                    const float* __restrict__ B, int btop) {
    // returns sum_j A[abase + j] * B[btop - j]
    float s0 = 0.f, s1 = 0.f, s2 = 0.f, s3 = 0.f;
    #pragma unroll
    for (int j = 0; j < AR_P; j += 4) {
        s0 += A[abase + j + 0] * B[btop - j - 0];
        s1 += A[abase + j + 1] * B[btop - j - 1];
        s2 += A[abase + j + 2] * B[btop - j - 2];
        s3 += A[abase + j + 3] * B[btop - j - 3];
    }
    return (s0 + s1) + (s2 + s3);
}

// ---------------------------------------------------------------------------
// Kernel 1 (single block, 1024 thr): impulse response by doubling,
// prefix sum, per-chunk boundary projections.
// ---------------------------------------------------------------------------
__global__ __launch_bounds__(1024) void k1_prep(const float* __restrict__ params,
                                                const float* __restrict__ bias) {
    __shared__ __align__(16) float Pp[2 * AR_P];        // params + 64 zeros
    __shared__ __align__(16) float hs[AR_P + CHUNK_L];  // padded impulse response
    __shared__ __align__(16) float phi[AR_P];
    __shared__ float red[32];
    __shared__ float stA[AR_P], stB[AR_P];

    const int tid = threadIdx.x;
    const int lane = tid & 31;
    const float bv = bias[0];

    if (tid < 2 * AR_P) Pp[tid] = (tid < AR_P) ? params[tid] : 0.0f;
    if (tid < AR_P) hs[tid] = 0.0f;          // left zero pad h_{-64..-1}
    if (tid == 0) hs[AR_P] = 1.0f;           // h_0 = 1
    __syncthreads();

    // ---- levels n = 1..32 : scalar, warp 0 only ----
    if (tid < 32) {
        for (int n = 1; n < AR_P; n <<= 1) {
            #pragma unroll 2
            for (int i = lane; i < AR_P; i += 32)
                phi[i] = dot64_4acc_fwd_rev(Pp, i, hs, AR_P + n - 1);
            __syncwarp();
            if (lane < n)
                hs[AR_P + n + lane] = dot64_4acc_fwd_rev(phi, 0, hs, AR_P + lane);
            __syncwarp();
        }
        // ---- levels n = 64, 128 : float4 path, still warp 0 ----
        for (int n = AR_P; n < 256; n <<= 1) {
            #pragma unroll 2
            for (int i = lane; i < AR_P; i += 32)
                phi[i] = dot64_4acc_fwd_rev(Pp, i, hs, AR_P + n - 1);
            __syncwarp();
            const int nt = n >> 2;
            for (int t = lane; t < nt; t += 32) {
                float a0, a1, a2, a3;
                conv4_f4(hs, AR_P + 4 * t, phi, a0, a1, a2, a3);
                *reinterpret_cast<float4*>(&hs[AR_P + n + 4 * t]) =
                    make_float4(a0, a1, a2, a3);
            }
            __syncwarp();
        }
    }
    __syncthreads();

    // ---- levels n = 256 .. 4096 : full block ----
    for (int n = 256; n < CHUNK_L; n <<= 1) {
        if (tid < AR_P)
            phi[tid] = dot64_4acc_fwd_rev(Pp, tid, hs, AR_P + n - 1);
        __syncthreads();
        const int nt = n >> 2;
        if (tid < nt) {
            float a0, a1, a2, a3;
            conv4_f4(hs, AR_P + 4 * tid, phi, a0, a1, a2, a3);
            *reinterpret_cast<float4*>(&hs[AR_P + n + 4 * tid]) =
                make_float4(a0, a1, a2, a3);
        }
        __syncthreads();
    }

    // ---- write padded h to global (float4) ----
    {
        const float4* s4 = reinterpret_cast<const float4*>(hs);
        float4* d4 = reinterpret_cast<float4*>(g_hpad);
        for (int q = tid; q < (AR_P + CHUNK_L) / 4; q += 1024) d4[q] = s4[q];
    }

    // ---- inclusive prefix sum of h -> g_H (8 elems/thread) ----
    float v[8];
    float s = 0.0f;
    #pragma unroll
    for (int k = 0; k < 8; k++) { v[k] = hs[AR_P + tid * 8 + k]; s += v[k]; }
    float ss = s;
    #pragma unroll
    for (int o = 1; o < 32; o <<= 1) {
        const float t2 = __shfl_up_sync(0xffffffffu, ss, o);
        if (lane >= o) ss += t2;
    }
    if (lane == 31) red[tid >> 5] = ss;
    __syncthreads();
    if (tid < 32) {
        float ws = red[tid];
        #pragma unroll
        for (int o = 1; o < 32; o <<= 1) {
            const float t2 = __shfl_up_sync(0xffffffffu, ws, o);
            if (tid >= o) ws += t2;
        }
        red[tid] = ws;
    }
    __syncthreads();
    float run = (ss - s) + ((tid >= 32) ? red[(tid >> 5) - 1] : 0.0f);
    #pragma unroll
    for (int k = 0; k < 8; k++) { run += v[k]; g_H[tid * 8 + k] = run; }
    __syncthreads();

    // ---- sequential hop over the 8 chunk-boundary states ----
    if (tid < AR_P) stA[tid] = 0.0f;          // state[j] = x_{cL-1-j}
    __syncthreads();
    float* scur = stA;
    float* snew = stB;
    for (int c = 0; c < N_CHUNKS; c++) {
        if (tid < AR_P) {
            // phi_i = sum_j a_{i+j} * state[j]   (state stored most-recent-first)
            float s0 = 0.f, s1 = 0.f, s2 = 0.f, s3 = 0.f;
            #pragma unroll
            for (int j = 0; j < AR_P; j += 4) {
                s0 += Pp[tid + j + 0] * scur[j + 0];
                s1 += Pp[tid + j + 1] * scur[j + 1];
                s2 += Pp[tid + j + 2] * scur[j + 2];
                s3 += Pp[tid + j + 3] * scur[j + 3];
            }
            const float ph = (s0 + s1) + (s2 + s3);
            phi[tid] = ph;
            g_phi[c][tid] = ph;
        }
        __syncthreads();
        if (c < N_CHUNKS - 1) {
            if (tid < AR_P) {
                const int m = CHUNK_L - 1 - tid;   // new state[j] = x_{(c+1)L-1-j}
                const float acc = dot64_4acc_fwd_rev(phi, 0, hs, AR_P + m);
                snew[tid] = acc + bv * g_H[m];
            }
            __syncthreads();
            float* tmp = scur; scur = snew; snew = tmp;
        }
    }
}

// ---------------------------------------------------------------------------
// Kernel 2: fill all means. grid = 64 blocks x 256 threads,
// 4 consecutive outputs per thread, conflict-free float4 windows.
// ---------------------------------------------------------------------------
__global__ __launch_bounds__(256) void k2_means(const float* __restrict__ bias) {
    const int c = blockIdx.x >> 3;
    const int part = blockIdx.x & 7;
    const int m0base = part * 1024;

    __shared__ __align__(16) float phi[AR_P];
    __shared__ __align__(16) float hw[1088];   // h_{m0base-64 .. m0base+1023}

    const int tid = threadIdx.x;
    if (tid < AR_P) phi[tid] = g_phi[c][tid];
    {
        const float4* g4 = reinterpret_cast<const float4*>(&g_hpad[m0base]);
        float4* s4 = reinterpret_cast<float4*>(hw);
        for (int q = tid; q < 1088 / 4; q += 256) s4[q] = g4[q];
    }
    __syncthreads();

    const float bv = bias[0];
    const int d = tid * 4;
    float a0, a1, a2, a3;
    conv4_f4(hw, 64 + d, phi, a0, a1, a2, a3);

    const int m = m0base + d;
    const float4 Hv = *reinterpret_cast<const float4*>(&g_H[m]);
    float4 r;
    r.x = fmaf(bv, Hv.x, a0);
    r.y = fmaf(bv, Hv.y, a1);
    r.z = fmaf(bv, Hv.z, a2);
    r.w = fmaf(bv, Hv.w, a3);
    *reinterpret_cast<float4*>(&g_means[c * CHUNK_L + m]) = r;
}

// ---------------------------------------------------------------------------
// Kernel 3: out[b,t] = means[t] + 0.3*noise[b,t]  (float4 streaming, .cs hints)
// ---------------------------------------------------------------------------
__global__ __launch_bounds__(256) void k3_out(const float4* __restrict__ noise,
                                              float4* __restrict__ out) {
    const int idx = blockIdx.x * 256 + threadIdx.x;
    const int t4 = idx & (AR_T / 4 - 1);
    const float4 nz = __ldcs(&noise[idx]);                       // stream, don't cache
    const float4 mn = reinterpret_cast<const float4*>(g_means)[t4];  // L2-resident
    float4 r;
    r.x = fmaf(0.3f, nz.x, mn.x);
    r.y = fmaf(0.3f, nz.y, mn.y);
    r.z = fmaf(0.3f, nz.z, mn.z);
    r.w = fmaf(0.3f, nz.w, mn.w);
    __stcs(&out[idx], r);                                        // evict-first store
}

extern "C" void kernel_launch(void* const* d_in, const int* in_sizes, int n_in,
                              void* d_out, int out_size) {
    // identify inputs by element count (params=64, bias=1, noise=256*65536)
    const float* params = nullptr;
    const float* bias   = nullptr;
    const float* noise  = nullptr;
    for (int i = 0; i < n_in; i++) {
        if (in_sizes[i] == AR_P)      params = (const float*)d_in[i];
        else if (in_sizes[i] == 1)    bias   = (const float*)d_in[i];
        else                          noise  = (const float*)d_in[i];
    }

    k1_prep<<<1, 1024>>>(params, bias);
    k2_means<<<N_CHUNKS * 8, 256>>>(bias);

    const int total4 = out_size / 4;          // 4,194,304 float4s
    k3_out<<<total4 / 256, 256>>>((const float4*)noise, (float4*)d_out);
}